// round 7
// baseline (speedup 1.0000x reference)
#include <cuda_runtime.h>
#include <cstdint>
#include <math.h>

#define SEQ   2048
#define BATCH 64
#define INP   256
#define HID   256

typedef unsigned long long ull;

// ---------- packed f32x2 helpers (Blackwell FFMA2 path, PTX-only) ----------
__device__ __forceinline__ void ffma2(ull& d, ull a, ull b) {
    asm("fma.rn.f32x2 %0, %1, %2, %0;" : "+l"(d) : "l"(a), "l"(b));
}
__device__ __forceinline__ ull pk(float a, float b) {
    ull r; asm("mov.b64 %0, {%1, %2};" : "=l"(r) : "f"(a), "f"(b)); return r;
}
__device__ __forceinline__ float2 unpk(ull v) {
    float x, y; asm("mov.b64 {%0, %1}, %2;" : "=f"(x), "=f"(y) : "l"(v));
    return make_float2(x, y);
}

__device__ __forceinline__ unsigned smem_u32(const void* p) {
    unsigned a;
    asm("{ .reg .u64 t; cvta.to.shared.u64 t, %1; cvt.u32.u64 %0, t; }"
        : "=r"(a) : "l"(p));
    return a;
}
__device__ __forceinline__ unsigned mapa_peer(unsigned local_addr, unsigned peer) {
    unsigned r;
    asm("mapa.shared::cluster.u32 %0, %1, %2;" : "=r"(r) : "r"(local_addr), "r"(peer));
    return r;
}

// Branch-free tanh: 1 - 2/(e^{2x}+1).  ex2/rcp approx, abs err ~1e-7.
__device__ __forceinline__ float fast_tanh(float x) {
    float e;
    asm("ex2.approx.ftz.f32 %0, %1;" : "=f"(e) : "f"(x * 2.8853900817779268f)); // 2*log2(e)
    float r;
    asm("rcp.approx.ftz.f32 %0, %1;" : "=f"(r) : "f"(e + 1.0f));
    return fmaf(-2.0f, r, 1.0f);
}

// =====================================================================
// Phase 1: xp[t,b,h] = sum_i x[t,b,i] * W_ih[h,i] + b_ih[h] + b_hh[h]
// One CTA per t. 256 threads. (~350us)
// =====================================================================
__global__ __launch_bounds__(256) void xp_gemm_kernel(
    const float* __restrict__ x,
    const float* __restrict__ Wih,
    const float* __restrict__ bih,
    const float* __restrict__ bhh,
    float* __restrict__ out)
{
    __shared__ float Xs[32][68];
    __shared__ float Ws[32][257];

    const int t   = blockIdx.x;
    const int tid = threadIdx.x;
    const int tn  = tid & 31;
    const int tm  = tid >> 5;
    const int m0  = tm * 8;

    const float* xt = x + (size_t)t * BATCH * INP;

    ull acc[8][4];
    #pragma unroll
    for (int u = 0; u < 8; ++u)
        #pragma unroll
        for (int v = 0; v < 4; ++v) acc[u][v] = 0ull;

    for (int kc = 0; kc < INP; kc += 32) {
        #pragma unroll
        for (int r = 0; r < 2; ++r) {
            int idx = tid + 256 * r;
            int m   = idx >> 3;
            int k4  = (idx & 7) * 4;
            float4 v = *(const float4*)(xt + (size_t)m * INP + kc + k4);
            Xs[k4 + 0][m] = v.x; Xs[k4 + 1][m] = v.y;
            Xs[k4 + 2][m] = v.z; Xs[k4 + 3][m] = v.w;
        }
        #pragma unroll
        for (int r = 0; r < 8; ++r) {
            int idx = tid + 256 * r;
            int h   = idx >> 3;
            int k4  = (idx & 7) * 4;
            float4 v = *(const float4*)(Wih + (size_t)h * INP + kc + k4);
            Ws[k4 + 0][h] = v.x; Ws[k4 + 1][h] = v.y;
            Ws[k4 + 2][h] = v.z; Ws[k4 + 3][h] = v.w;
        }
        __syncthreads();

        #pragma unroll
        for (int k = 0; k < 32; ++k) {
            float4 a0 = *(const float4*)&Xs[k][m0];
            float4 a1 = *(const float4*)&Xs[k][m0 + 4];
            ull ap[8];
            ap[0] = pk(a0.x, a0.x); ap[1] = pk(a0.y, a0.y);
            ap[2] = pk(a0.z, a0.z); ap[3] = pk(a0.w, a0.w);
            ap[4] = pk(a1.x, a1.x); ap[5] = pk(a1.y, a1.y);
            ap[6] = pk(a1.z, a1.z); ap[7] = pk(a1.w, a1.w);

            float w[8];
            #pragma unroll
            for (int v = 0; v < 8; ++v) w[v] = Ws[k][tn + 32 * v];

            #pragma unroll
            for (int v2 = 0; v2 < 4; ++v2) {
                ull wp = pk(w[2 * v2], w[2 * v2 + 1]);
                #pragma unroll
                for (int u = 0; u < 8; ++u)
                    ffma2(acc[u][v2], wp, ap[u]);
            }
        }
        __syncthreads();
    }

    float ba[4], bb[4];
    #pragma unroll
    for (int v2 = 0; v2 < 4; ++v2) {
        int hA = tn + 64 * v2, hB = hA + 32;
        ba[v2] = bih[hA] + bhh[hA];
        bb[v2] = bih[hB] + bhh[hB];
    }
    float* ot = out + (size_t)t * BATCH * HID;
    #pragma unroll
    for (int u = 0; u < 8; ++u) {
        float* row = ot + (size_t)(m0 + u) * HID;
        #pragma unroll
        for (int v2 = 0; v2 < 4; ++v2) {
            float2 s = unpk(acc[u][v2]);
            row[tn + 64 * v2]      = s.x + ba[v2];
            row[tn + 64 * v2 + 32] = s.y + bb[v2];
        }
    }
}

// =====================================================================
// Phase 2: serial scan, v5 — 2-CTA cluster, flag-polling exchange.
// Cluster for batch b = CTAs {2b,2b+1}; rank r owns k in [128r,+128)
// and finalizes rows [128r,+128).
// Threads [0,256): RECEIVERS — row j = 128r + (tid>>1), compute local
//   partial, spin on LOCAL smem seqno flag, add remote partials, tanh.
// Threads [256,512): SENDERS (warps 8-15, hi-wid arbiter priority) —
//   row j = peer's rows, compute partial, st.shared::cluster into peer
//   recvbuf, named-bar(1,256), elected fence+flag store (seqno t+1).
// No mbarrier (UCGABAR_WAIT ~490 avoided); poll cost = local LDS.
// =====================================================================
#define WKP   32               // 32 ull pairs = 64 k-values per thread
#define HPAD  68               // padded stride of the s=1 h stream (floats)
#define HBUF  (HPAD + 64)      // 132 floats per h buffer

__global__ __launch_bounds__(512, 1) __cluster_dims__(2, 1, 1)
void rnn_scan_kernel(
    const float* __restrict__ Whh,  // [HID][HID]
    float* __restrict__ out)        // in: xp, out: h   [SEQ][BATCH][HID]
{
    __shared__ float hbuf[2 * HBUF];          // local rows' h, double buffered
    __shared__ float recvbuf[2 * 256];        // [parity][2*jj+s] peer partials
    __shared__ unsigned flagw[2 * 32];        // [parity*32] seqno flags (padded)

    const int bidx = blockIdx.x;
    const int b    = bidx >> 1;
    const int r    = bidx & 1;                // cluster rank
    const int tid  = threadIdx.x;
    const int role = tid >> 8;                // 0 = receiver, 1 = sender
    const int jj   = (tid >> 1) & 127;        // row index within a half
    const int s    = tid & 1;                 // k-subhalf

    // row whose partial this thread computes
    const int j = role ? (128 * (1 - r) + jj) : (128 * r + jj);

    // ---- register-resident W: W_hh[j][128r + 64s + 0..63] ----
    ull wreg[WKP];
    {
        const float* wrow = Whh + (size_t)j * HID + r * 128 + s * 64;
        #pragma unroll
        for (int p = 0; p < WKP; ++p)
            wreg[p] = *(const ull*)(wrow + 2 * p);
    }

    // ---- init smem ----
    if (tid < 2 * HBUF) hbuf[tid] = 0.f;
    if (tid < 64) flagw[tid] = 0u;
    __syncthreads();
    asm volatile("barrier.cluster.arrive.aligned;" ::: "memory");
    asm volatile("barrier.cluster.wait.aligned;"   ::: "memory");

    // ---- peer addresses ----
    const unsigned peer      = (unsigned)(r ^ 1);
    const unsigned recv_l    = smem_u32(recvbuf);
    const unsigned flag_l    = smem_u32(flagw);
    const unsigned peer_recv = mapa_peer(recv_l, peer);
    const unsigned peer_flag = mapa_peer(flag_l, peer);

    const size_t stride = (size_t)BATCH * HID;
    float* col = out + (size_t)b * HID + (128 * r + jj);  // receivers' row column

    float xpv = (role == 0) ? __ldcg(col) : 0.f;
    int cur = 0;

    const int hoff = s * HPAD;

    for (int t = 0; t < SEQ; ++t) {
        const int par = t & 1;

        // receiver: hoisted xp prefetch
        float xp_next = 0.f;
        if (role == 0 && t + 1 < SEQ)
            xp_next = __ldcg(col + (size_t)(t + 1) * stride);

        // ---- matvec partial over 64 k-values (4 accumulators) ----
        const ulonglong2* h2 = (const ulonglong2*)(hbuf + cur * HBUF + hoff);
        ull a0 = 0ull, a1 = 0ull, a2 = 0ull, a3 = 0ull;
        #pragma unroll
        for (int g = 0; g < 8; ++g) {
            ulonglong2 hA = h2[2 * g];
            ulonglong2 hB = h2[2 * g + 1];
            ffma2(a0, wreg[4 * g + 0], hA.x);
            ffma2(a1, wreg[4 * g + 1], hA.y);
            ffma2(a2, wreg[4 * g + 2], hB.x);
            ffma2(a3, wreg[4 * g + 3], hB.y);
        }
        float2 s0 = unpk(a0), s1 = unpk(a1), s2 = unpk(a2), s3 = unpk(a3);
        float part = ((s0.x + s0.y) + (s1.x + s1.y))
                   + ((s2.x + s2.y) + (s3.x + s3.y));

        if (role == 1) {
            // ---- sender: ship partial, then seqno flag ----
            unsigned a = peer_recv + (unsigned)par * 1024u
                                   + (unsigned)(2 * jj + s) * 4u;
            asm volatile("st.shared::cluster.f32 [%0], %1;"
                         :: "r"(a), "f"(part) : "memory");
            asm volatile("bar.sync 1, 256;" ::: "memory");   // all sender stores issued
            if (tid == 256) {
                asm volatile("fence.acq_rel.cluster;" ::: "memory");
                asm volatile("st.shared::cluster.u32 [%0], %1;"
                             :: "r"(peer_flag + (unsigned)par * 128u),
                                "r"((unsigned)(t + 1)) : "memory");
            }
        } else {
            // ---- receiver: combine own halves, wait for peer, finalize ----
            float tot = part + __shfl_xor_sync(0xFFFFFFFFu, part, 1);

            const unsigned fa = flag_l + (unsigned)par * 128u;
            unsigned v;
            do {
                asm volatile("ld.volatile.shared.u32 %0, [%1];"
                             : "=r"(v) : "r"(fa));
            } while ((int)v < t + 1);
            asm volatile("fence.acq_rel.cluster;" ::: "memory");

            float rem = recvbuf[par * 256 + 2 * jj]
                      + recvbuf[par * 256 + 2 * jj + 1];
            float val = fast_tanh(xpv + tot + rem);

            if (s == 0) {
                hbuf[(cur ^ 1) * HBUF + ((jj < 64) ? jj : (jj - 64 + HPAD))] = val;
            } else {
                col[(size_t)t * stride] = val;      // h_t -> gmem
            }
            xpv = xp_next;
        }

        __syncthreads();
        cur ^= 1;
    }

    asm volatile("barrier.cluster.arrive.aligned;" ::: "memory");
    asm volatile("barrier.cluster.wait.aligned;"   ::: "memory");
}

// =====================================================================
extern "C" void kernel_launch(void* const* d_in, const int* in_sizes, int n_in,
                              void* d_out, int out_size) {
    const float* x   = (const float*)d_in[0];  // [SEQ][BATCH][INP]
    const float* Wih = (const float*)d_in[1];  // [HID][INP]
    const float* Whh = (const float*)d_in[2];  // [HID][HID]
    const float* bih = (const float*)d_in[3];  // [HID]
    const float* bhh = (const float*)d_in[4];  // [HID]
    float* out = (float*)d_out;                // [SEQ][BATCH][HID]

    xp_gemm_kernel<<<SEQ, 256>>>(x, Wih, bih, bhh, out);
    rnn_scan_kernel<<<2 * BATCH, 512>>>(Whh, out);
}

// round 8
// speedup vs baseline: 1.4083x; 1.4083x over previous
#include <cuda_runtime.h>
#include <cstdint>
#include <math.h>

#define SEQ   2048
#define BATCH 64
#define INP   256
#define HID   256

typedef unsigned long long ull;

// ---------- packed f32x2 helpers (Blackwell FFMA2 path, PTX-only) ----------
__device__ __forceinline__ void ffma2(ull& d, ull a, ull b) {
    asm("fma.rn.f32x2 %0, %1, %2, %0;" : "+l"(d) : "l"(a), "l"(b));
}
__device__ __forceinline__ ull pk(float a, float b) {
    ull r; asm("mov.b64 %0, {%1, %2};" : "=l"(r) : "f"(a), "f"(b)); return r;
}
__device__ __forceinline__ ull pku(unsigned a, unsigned b) {
    ull r; asm("mov.b64 %0, {%1, %2};" : "=l"(r) : "r"(a), "r"(b)); return r;
}
__device__ __forceinline__ float2 unpk(ull v) {
    float x, y; asm("mov.b64 {%0, %1}, %2;" : "=f"(x), "=f"(y) : "l"(v));
    return make_float2(x, y);
}
__device__ __forceinline__ unsigned smem_u32(const void* p) {
    unsigned a;
    asm("{ .reg .u64 t; cvta.to.shared.u64 t, %1; cvt.u32.u64 %0, t; }"
        : "=r"(a) : "l"(p));
    return a;
}
__device__ __forceinline__ unsigned mapa_peer(unsigned local_addr, unsigned peer) {
    unsigned r;
    asm("mapa.shared::cluster.u32 %0, %1, %2;" : "=r"(r) : "r"(local_addr), "r"(peer));
    return r;
}
// Branch-free tanh: 1 - 2/(e^{2x}+1). ex2/rcp approx, abs err ~1e-7.
__device__ __forceinline__ float fast_tanh(float x) {
    float e;
    asm("ex2.approx.ftz.f32 %0, %1;" : "=f"(e) : "f"(x * 2.8853900817779268f));
    float r;
    asm("rcp.approx.ftz.f32 %0, %1;" : "=f"(r) : "f"(e + 1.0f));
    return fmaf(-2.0f, r, 1.0f);
}

// =====================================================================
// Phase 1: xp[t,b,h] = x[t,b]·W_ih[h] + b_ih[h] + b_hh[h]  (unchanged)
// =====================================================================
__global__ __launch_bounds__(256) void xp_gemm_kernel(
    const float* __restrict__ x,
    const float* __restrict__ Wih,
    const float* __restrict__ bih,
    const float* __restrict__ bhh,
    float* __restrict__ out)
{
    __shared__ float Xs[32][68];
    __shared__ float Ws[32][257];

    const int t   = blockIdx.x;
    const int tid = threadIdx.x;
    const int tn  = tid & 31;
    const int tm  = tid >> 5;
    const int m0  = tm * 8;

    const float* xt = x + (size_t)t * BATCH * INP;

    ull acc[8][4];
    #pragma unroll
    for (int u = 0; u < 8; ++u)
        #pragma unroll
        for (int v = 0; v < 4; ++v) acc[u][v] = 0ull;

    for (int kc = 0; kc < INP; kc += 32) {
        #pragma unroll
        for (int r = 0; r < 2; ++r) {
            int idx = tid + 256 * r;
            int m   = idx >> 3;
            int k4  = (idx & 7) * 4;
            float4 v = *(const float4*)(xt + (size_t)m * INP + kc + k4);
            Xs[k4 + 0][m] = v.x; Xs[k4 + 1][m] = v.y;
            Xs[k4 + 2][m] = v.z; Xs[k4 + 3][m] = v.w;
        }
        #pragma unroll
        for (int r = 0; r < 8; ++r) {
            int idx = tid + 256 * r;
            int h   = idx >> 3;
            int k4  = (idx & 7) * 4;
            float4 v = *(const float4*)(Wih + (size_t)h * INP + kc + k4);
            Ws[k4 + 0][h] = v.x; Ws[k4 + 1][h] = v.y;
            Ws[k4 + 2][h] = v.z; Ws[k4 + 3][h] = v.w;
        }
        __syncthreads();

        #pragma unroll
        for (int k = 0; k < 32; ++k) {
            float4 a0 = *(const float4*)&Xs[k][m0];
            float4 a1 = *(const float4*)&Xs[k][m0 + 4];
            ull ap[8];
            ap[0] = pk(a0.x, a0.x); ap[1] = pk(a0.y, a0.y);
            ap[2] = pk(a0.z, a0.z); ap[3] = pk(a0.w, a0.w);
            ap[4] = pk(a1.x, a1.x); ap[5] = pk(a1.y, a1.y);
            ap[6] = pk(a1.z, a1.z); ap[7] = pk(a1.w, a1.w);

            float w[8];
            #pragma unroll
            for (int v = 0; v < 8; ++v) w[v] = Ws[k][tn + 32 * v];

            #pragma unroll
            for (int v2 = 0; v2 < 4; ++v2) {
                ull wp = pk(w[2 * v2], w[2 * v2 + 1]);
                #pragma unroll
                for (int u = 0; u < 8; ++u)
                    ffma2(acc[u][v2], wp, ap[u]);
            }
        }
        __syncthreads();
    }

    float ba[4], bb[4];
    #pragma unroll
    for (int v2 = 0; v2 < 4; ++v2) {
        int hA = tn + 64 * v2, hB = hA + 32;
        ba[v2] = bih[hA] + bhh[hA];
        bb[v2] = bih[hB] + bhh[hB];
    }
    float* ot = out + (size_t)t * BATCH * HID;
    #pragma unroll
    for (int u = 0; u < 8; ++u) {
        float* row = ot + (size_t)(m0 + u) * HID;
        #pragma unroll
        for (int v2 = 0; v2 < 4; ++v2) {
            float2 s = unpk(acc[u][v2]);
            row[tn + 64 * v2]      = s.x + ba[v2];
            row[tn + 64 * v2 + 32] = s.y + bb[v2];
        }
    }
}

// =====================================================================
// Phase 2: serial scan, v6 — h-exchange via atomic (val,seq) pairs.
// Cluster {2b,2b+1}; rank r finalizes rows [128r,+128), computing the
// FULL 256-k matvec for them. 512 threads: jj=tid&127 (row), g=tid>>7:
//   g0: k in [128r,    +64)   local h (smem hbuf)     + finalizer
//   g1: k in [128r+64, +64)   local h
//   g2: k in [128r'+0, +64)   peer h (pairbuf pairs)
//   g3: k in [128r'+64,+64)   peer h
// W: 32 ull regs/thread. Partials -> pbuf, BAR, g0 finalizes: tanh,
// STS local h, STG, and st.shared::cluster.u64 {h, t+1} into peer's
// pairbuf (parity t&1). Receivers ballot-poll seqnos (local LDS) ==
// t, then bulk-read. No fences/mbarriers at all: 8B store atomicity +
// seqno-in-payload + provable no-overwrite (peer needs my h_t before
// it can send h_{t+1} into the same parity slots).
// =====================================================================
__global__ __launch_bounds__(512, 1) __cluster_dims__(2, 1, 1)
void rnn_scan_kernel(
    const float* __restrict__ Whh,  // [HID][HID]
    float* __restrict__ out)        // in: xp, out: h   [SEQ][BATCH][HID]
{
    __shared__ float pbuf[512];                    // partials [jj*4+g]
    __shared__ float hbuf[2 * 128];                // local rows' h by parity
    __shared__ alignas(16) ull pairbuf[2 * 128];   // peer h pairs {f32,seq} by parity

    const int bidx = blockIdx.x;
    const int b    = bidx >> 1;
    const int r    = bidx & 1;             // cluster rank
    const int tid  = threadIdx.x;
    const int jj   = tid & 127;            // row within my half
    const int g    = tid >> 7;             // k-window group
    const int lane = tid & 31;
    const int j    = 128 * r + jj;         // global row I contribute to

    const int koff = (g < 2) ? (128 * r + 64 * g)
                             : (128 * (1 - r) + 64 * (g - 2));

    // ---- register-resident W: W_hh[j][koff + 0..63] ----
    ull wreg[32];
    {
        const float* wrow = Whh + (size_t)j * HID + koff;
        #pragma unroll
        for (int p = 0; p < 32; ++p)
            wreg[p] = *(const ull*)(wrow + 2 * p);
    }

    // ---- init smem ----
    if (tid < 256) hbuf[tid] = 0.f;
    if (tid < 256) pairbuf[tid] = 0ull;    // val=0, seq=0 (passes t=0 check)
    __syncthreads();
    asm volatile("barrier.cluster.arrive.aligned;" ::: "memory");
    asm volatile("barrier.cluster.wait.aligned;"   ::: "memory");

    const unsigned peer      = (unsigned)(r ^ 1);
    const unsigned pair_l    = smem_u32(pairbuf);
    const unsigned peer_pair = mapa_peer(pair_l, peer);

    const size_t stride = (size_t)BATCH * HID;
    float* col = out + (size_t)b * HID + j;

    // xp prefetch queue, depth 2 (finalizers only)
    float xq0 = 0.f, xq1 = 0.f;
    if (g == 0) {
        xq0 = __ldcg(col);
        xq1 = __ldcg(col + stride);
    }

    for (int t = 0; t < SEQ; ++t) {
        const int sp = t & 1;          // send parity (h_t)
        const int rp = sp ^ 1;         // read parity (h_{t-1})

        // ---- matvec partial over my 64 k-values ----
        ull a0 = 0ull, a1 = 0ull, a2 = 0ull, a3 = 0ull;
        if (g < 2) {
            // local h, broadcast LDS.128 stream
            const ulonglong2* h2 =
                (const ulonglong2*)(hbuf + rp * 128 + 64 * g);
            #pragma unroll
            for (int q = 0; q < 16; ++q) {
                ulonglong2 h = h2[q];
                if (q & 1) { ffma2(a2, wreg[2 * q], h.x);
                             ffma2(a3, wreg[2 * q + 1], h.y); }
                else       { ffma2(a0, wreg[2 * q], h.x);
                             ffma2(a1, wreg[2 * q + 1], h.y); }
            }
        } else {
            // peer h: poll seqnos, then bulk-read pairs
            const unsigned base = pair_l + (unsigned)rp * 1024u
                                         + (unsigned)(g - 2) * 512u;
            const unsigned aA = base + (unsigned)lane * 8u;
            const unsigned aB = aA + 256u;
            const unsigned T  = (unsigned)t;
            unsigned ok;
            do {
                ull p1, p2;
                asm volatile("ld.volatile.shared.u64 %0, [%1];"
                             : "=l"(p1) : "r"(aA) : "memory");
                asm volatile("ld.volatile.shared.u64 %0, [%1];"
                             : "=l"(p2) : "r"(aB) : "memory");
                ok = ((unsigned)(p1 >> 32) == T) & ((unsigned)(p2 >> 32) == T);
            } while (__all_sync(0xFFFFFFFFu, ok) == 0);

            const uint4* pq = (const uint4*)((const char*)pairbuf
                               + rp * 1024 + (g - 2) * 512);
            #pragma unroll
            for (int q = 0; q < 16; ++q) {
                uint4 vA = pq[2 * q];        // {h0,s0,h1,s1}
                uint4 vB = pq[2 * q + 1];
                ffma2(a0, wreg[2 * q],     pku(vA.x, vA.z));
                ffma2(a1, wreg[2 * q + 1], pku(vB.x, vB.z));
            }
            // fold a1 usage symmetry: keep 2 accs busy, a2/a3 stay 0
        }
        float2 s0 = unpk(a0), s1 = unpk(a1), s2 = unpk(a2), s3 = unpk(a3);
        pbuf[4 * jj + g] = ((s0.x + s0.y) + (s1.x + s1.y))
                         + ((s2.x + s2.y) + (s3.x + s3.y));

        __syncthreads();   // BAR1: all partials visible

        if (g == 0) {
            float4 ps = *(const float4*)(pbuf + 4 * jj);
            float val = fast_tanh(xq0 + ((ps.x + ps.y) + (ps.z + ps.w)));

            // 1) ship h to peer FIRST (starts ~215cyc transit early)
            if (t + 1 < SEQ) {
                ull pv = pku(__float_as_uint(val), (unsigned)(t + 1));
                asm volatile("st.shared::cluster.u64 [%0], %1;"
                             :: "r"(peer_pair + (unsigned)sp * 1024u
                                              + (unsigned)jj * 8u),
                                "l"(pv) : "memory");
            }
            // 2) local h for next step
            hbuf[sp * 128 + jj] = val;
            // 3) output
            col[(size_t)t * stride] = val;
            // 4) advance xp queue
            xq0 = xq1;
            if (t + 2 < SEQ) xq1 = __ldcg(col + (size_t)(t + 2) * stride);
        }

        __syncthreads();   // BAR2: h/pbuf safe for next step
    }

    asm volatile("barrier.cluster.arrive.aligned;" ::: "memory");
    asm volatile("barrier.cluster.wait.aligned;"   ::: "memory");
}

// =====================================================================
extern "C" void kernel_launch(void* const* d_in, const int* in_sizes, int n_in,
                              void* d_out, int out_size) {
    const float* x   = (const float*)d_in[0];  // [SEQ][BATCH][INP]
    const float* Wih = (const float*)d_in[1];  // [HID][INP]
    const float* Whh = (const float*)d_in[2];  // [HID][HID]
    const float* bih = (const float*)d_in[3];  // [HID]
    const float* bhh = (const float*)d_in[4];  // [HID]
    float* out = (float*)d_out;                // [SEQ][BATCH][HID]

    xp_gemm_kernel<<<SEQ, 256>>>(x, Wih, bih, bhh, out);
    rnn_scan_kernel<<<2 * BATCH, 512>>>(Whh, out);
}